// round 1
// baseline (speedup 1.0000x reference)
#include <cuda_runtime.h>
#include <cuda_bf16.h>
#include <math.h>

// Problem constants
#define BATCH 1024
#define ZDIM  512
#define ADIM  8
#define AH    64
#define ZH    512
#define NNEG  100           // shifts 1..99 -> 99 extra columns
#define NCOLS 1123          // 1024 + 99
#define LDSIM 1152          // padded row stride for sim_mat

// ---------------- device scratch (no allocs allowed) ----------------
__device__ float d_ha0[BATCH * AH];
__device__ float d_g[BATCH * ZH];
__device__ float d_zwb[BATCH * ZH];
__device__ float d_u[BATCH * ZDIM];
__device__ float d_simmat[BATCH * LDSIM];
__device__ float d_rowlog[BATCH];
__device__ int   d_rowcnt[BATCH];

// ---------------- ha0 = relu(actions @ Wa + ba) ----------------
__global__ void k_ha0(const float* __restrict__ actions,
                      const float* __restrict__ Wa,
                      const float* __restrict__ ba,
                      float* __restrict__ ha0) {
    int b = blockIdx.x;
    int h = threadIdx.x;   // 64 threads
    float s = ba[h];
#pragma unroll
    for (int a = 0; a < ADIM; a++)
        s += actions[b * ADIM + a] * Wa[a * AH + h];
    ha0[b * AH + h] = fmaxf(s, 0.f);
}

// ---------------- generic fp32 GEMM, 64x64x16 tile, 4x4 microtile ----------------
// C[M,N] = A[M,K] @ (TRANSB ? B^T : B) (+ bias[n] if BIAS)
// TRANSB: B is [N,K] row-major. else B is [K,N] row-major.
template <bool TRANSB, bool BIAS>
__global__ void gemm64(const float* __restrict__ A, const float* __restrict__ B,
                       const float* __restrict__ bias, float* __restrict__ C,
                       int M, int N, int K, int lda, int ldb, int ldc) {
    __shared__ float As[16][65];
    __shared__ float Bs[16][65];

    const int tid = threadIdx.x;          // 256 threads
    const int tx = tid & 15;              // n micro index
    const int ty = tid >> 4;              // m micro index
    const int m0 = blockIdx.y * 64;
    const int n0 = blockIdx.x * 64;

    // A-tile loader indices: 64 rows x 16 cols as float4
    const int ar = tid >> 2;              // 0..63
    const int ac = (tid & 3) * 4;         // 0,4,8,12
    // B-tile (NN) loader: 16 rows x 64 cols as float4
    const int br = tid >> 4;              // 0..15
    const int bc = (tid & 15) * 4;        // 0..60

    float acc[4][4];
#pragma unroll
    for (int i = 0; i < 4; i++)
#pragma unroll
        for (int j = 0; j < 4; j++) acc[i][j] = 0.f;

    for (int k0 = 0; k0 < K; k0 += 16) {
        float4 av = *(const float4*)(A + (size_t)(m0 + ar) * lda + k0 + ac);
        As[ac + 0][ar] = av.x; As[ac + 1][ar] = av.y;
        As[ac + 2][ar] = av.z; As[ac + 3][ar] = av.w;
        if (TRANSB) {
            float4 bv = *(const float4*)(B + (size_t)(n0 + ar) * ldb + k0 + ac);
            Bs[ac + 0][ar] = bv.x; Bs[ac + 1][ar] = bv.y;
            Bs[ac + 2][ar] = bv.z; Bs[ac + 3][ar] = bv.w;
        } else {
            float4 bv = *(const float4*)(B + (size_t)(k0 + br) * ldb + n0 + bc);
            Bs[br][bc + 0] = bv.x; Bs[br][bc + 1] = bv.y;
            Bs[br][bc + 2] = bv.z; Bs[br][bc + 3] = bv.w;
        }
        __syncthreads();
#pragma unroll
        for (int kk = 0; kk < 16; kk++) {
            float ra[4], rb[4];
#pragma unroll
            for (int i = 0; i < 4; i++) ra[i] = As[kk][ty * 4 + i];
#pragma unroll
            for (int j = 0; j < 4; j++) rb[j] = Bs[kk][tx * 4 + j];
#pragma unroll
            for (int i = 0; i < 4; i++)
#pragma unroll
                for (int j = 0; j < 4; j++) acc[i][j] += ra[i] * rb[j];
        }
        __syncthreads();
    }

#pragma unroll
    for (int i = 0; i < 4; i++) {
#pragma unroll
        for (int j = 0; j < 4; j++) {
            float v = acc[i][j];
            int n = n0 + tx * 4 + j;
            if (BIAS) v += bias[n];
            C[(size_t)(m0 + ty * 4 + i) * ldc + n] = v;
        }
    }
}

// ---------------- neg_sim: sim_mat[b, 1024+i-1] ----------------
// neg_sim[b,i] = dot(z[b],z_next[b]) + dot(b2,z_next[b])
//              + sum_k relu(zwb[b,k] + g[(b+i)%B, k]) * u[b,k]
__global__ void k_neg(const float* __restrict__ z, const float* __restrict__ zn,
                      const float* __restrict__ b2,
                      const float* __restrict__ zwb, const float* __restrict__ g,
                      const float* __restrict__ u, float* __restrict__ simmat) {
    int b = blockIdx.x;
    int tid = threadIdx.x;   // 256
    __shared__ float s_zwb[ZH];
    __shared__ float s_u[ZH];
    __shared__ float red[8];
    __shared__ float s_base;

    float czz = 0.f, bz = 0.f;
    for (int k = tid; k < ZH; k += 256) {
        float znv = zn[b * ZDIM + k];
        czz += z[b * ZDIM + k] * znv;
        bz  += b2[k] * znv;
        s_zwb[k] = zwb[b * ZH + k];
        s_u[k]   = u[b * ZDIM + k];
    }
    float t = czz + bz;
#pragma unroll
    for (int o = 16; o; o >>= 1) t += __shfl_xor_sync(0xffffffffu, t, o);
    if ((tid & 31) == 0) red[tid >> 5] = t;
    __syncthreads();
    if (tid == 0) {
        float s = 0.f;
#pragma unroll
        for (int w = 0; w < 8; w++) s += red[w];
        s_base = s;
    }
    __syncthreads();
    float base = s_base;

    int wid = tid >> 5, lane = tid & 31;
    for (int i = 1 + wid; i < NNEG; i += 8) {
        int row = (b + i) & (BATCH - 1);
        const float* gr = g + (size_t)row * ZH;
        float p = 0.f;
#pragma unroll
        for (int k = lane; k < ZH; k += 32)
            p += fmaxf(s_zwb[k] + gr[k], 0.f) * s_u[k];
#pragma unroll
        for (int o = 16; o; o >>= 1) p += __shfl_xor_sync(0xffffffffu, p, o);
        if (lane == 0) simmat[(size_t)b * LDSIM + (BATCH - 1) + i] = base + p;
    }
}

// ---------------- per-row log-softmax diag + rank count ----------------
__global__ void k_row(const float* __restrict__ simmat,
                      float* __restrict__ rowlog, int* __restrict__ rowcnt) {
    int b = blockIdx.x;
    int tid = threadIdx.x;   // 256
    const float* row = simmat + (size_t)b * LDSIM;
    float s = row[b];

    __shared__ float smx[8];
    __shared__ int   scn[8];
    __shared__ float ssm[8];
    __shared__ float s_mx;

    float mx = -INFINITY;
    int cnt = 0;
    for (int j = tid; j < NCOLS; j += 256) {
        float v = row[j];
        mx = fmaxf(mx, v);
        cnt += (v > s) || (v == s && j < b);
    }
#pragma unroll
    for (int o = 16; o; o >>= 1) {
        mx = fmaxf(mx, __shfl_xor_sync(0xffffffffu, mx, o));
        cnt += __shfl_xor_sync(0xffffffffu, cnt, o);
    }
    if ((tid & 31) == 0) { smx[tid >> 5] = mx; scn[tid >> 5] = cnt; }
    __syncthreads();
    if (tid == 0) {
        float m = smx[0]; int c = scn[0];
#pragma unroll
        for (int w = 1; w < 8; w++) { m = fmaxf(m, smx[w]); c += scn[w]; }
        s_mx = m;
        rowcnt[b] = c;
    }
    __syncthreads();
    float m = s_mx;

    float se = 0.f;
    for (int j = tid; j < NCOLS; j += 256)
        se += __expf((row[j] - m) * 10.f);
#pragma unroll
    for (int o = 16; o; o >>= 1) se += __shfl_xor_sync(0xffffffffu, se, o);
    if ((tid & 31) == 0) ssm[tid >> 5] = se;
    __syncthreads();
    if (tid == 0) {
        float t = 0.f;
#pragma unroll
        for (int w = 0; w < 8; w++) t += ssm[w];
        // logp[b,b] = s/T - (m/T + log(sum exp((v-m)/T)))
        rowlog[b] = (s - m) * 10.f - logf(t);
    }
}

// ---------------- final reduction over rows ----------------
__global__ void k_final(const float* __restrict__ rowlog,
                        const int* __restrict__ rowcnt,
                        float* __restrict__ out) {
    int tid = threadIdx.x;  // 1024
    float lg = rowlog[tid];
    int c = rowcnt[tid];
    float a1 = (c < 1) ? 1.f : 0.f;
    float a3 = (c < 3) ? 1.f : 0.f;
    float a10 = (c < 10) ? 1.f : 0.f;

    __shared__ float s0[32], s1[32], s2[32], s3[32];
#pragma unroll
    for (int o = 16; o; o >>= 1) {
        lg  += __shfl_xor_sync(0xffffffffu, lg, o);
        a1  += __shfl_xor_sync(0xffffffffu, a1, o);
        a3  += __shfl_xor_sync(0xffffffffu, a3, o);
        a10 += __shfl_xor_sync(0xffffffffu, a10, o);
    }
    int wid = tid >> 5, lane = tid & 31;
    if (lane == 0) { s0[wid] = lg; s1[wid] = a1; s2[wid] = a3; s3[wid] = a10; }
    __syncthreads();
    if (wid == 0) {
        float v0 = s0[lane], v1 = s1[lane], v2 = s2[lane], v3 = s3[lane];
#pragma unroll
        for (int o = 16; o; o >>= 1) {
            v0 += __shfl_xor_sync(0xffffffffu, v0, o);
            v1 += __shfl_xor_sync(0xffffffffu, v1, o);
            v2 += __shfl_xor_sync(0xffffffffu, v2, o);
            v3 += __shfl_xor_sync(0xffffffffu, v3, o);
        }
        if (lane == 0) {
            out[0] = -v0 / (float)BATCH;
            out[1] = v1 / (float)BATCH;
            out[2] = v2 / (float)BATCH;
            out[3] = v3 / (float)BATCH;
        }
    }
}

// ---------------- launch ----------------
extern "C" void kernel_launch(void* const* d_in, const int* in_sizes, int n_in,
                              void* d_out, int out_size) {
    const float* z          = (const float*)d_in[0];
    const float* z_next     = (const float*)d_in[1];
    const float* z_next_hat = (const float*)d_in[2];
    const float* actions    = (const float*)d_in[3];
    const float* Wa         = (const float*)d_in[4];
    const float* ba         = (const float*)d_in[5];
    const float* W1         = (const float*)d_in[6];
    const float* b1         = (const float*)d_in[7];
    const float* W2         = (const float*)d_in[8];
    const float* b2         = (const float*)d_in[9];
    float* out = (float*)d_out;

    float *ha0, *g, *zwb, *u, *simmat, *rowlog;
    int* rowcnt;
    cudaGetSymbolAddress((void**)&ha0, d_ha0);
    cudaGetSymbolAddress((void**)&g, d_g);
    cudaGetSymbolAddress((void**)&zwb, d_zwb);
    cudaGetSymbolAddress((void**)&u, d_u);
    cudaGetSymbolAddress((void**)&simmat, d_simmat);
    cudaGetSymbolAddress((void**)&rowlog, d_rowlog);
    cudaGetSymbolAddress((void**)&rowcnt, d_rowcnt);

    // 1. ha0 = relu(actions @ Wa + ba)           [1024, 64]
    k_ha0<<<BATCH, AH>>>(actions, Wa, ba, ha0);

    // 2. g = ha0 @ W1[512:576, :]                [1024, 512]
    gemm64<false, false><<<dim3(ZH / 64, BATCH / 64), 256>>>(
        ha0, W1 + (size_t)ZDIM * ZH, nullptr, g, BATCH, ZH, AH, AH, ZH, ZH);

    // 3. zwb = z @ W1[0:512, :] + b1             [1024, 512]
    gemm64<false, true><<<dim3(ZH / 64, BATCH / 64), 256>>>(
        z, W1, b1, zwb, BATCH, ZH, ZDIM, ZDIM, ZH, ZH);

    // 4. u = z_next @ W2^T                       [1024, 512]
    gemm64<true, false><<<dim3(ZDIM / 64, BATCH / 64), 256>>>(
        z_next, W2, nullptr, u, BATCH, ZDIM, ZH, ZDIM, ZH, ZDIM);

    // 5. sim = z_next @ z_next_hat^T -> simmat[:, 0:1024]
    gemm64<true, false><<<dim3(BATCH / 64, BATCH / 64), 256>>>(
        z_next, z_next_hat, nullptr, simmat, BATCH, BATCH, ZDIM, ZDIM, ZDIM, LDSIM);

    // 6. neg_sim columns 1024..1122
    k_neg<<<BATCH, 256>>>(z, z_next, b2, zwb, g, u, simmat);

    // 7. per-row log-softmax diagonal + rank counts
    k_row<<<BATCH, 256>>>(simmat, rowlog, rowcnt);

    // 8. final scalar outputs
    k_final<<<1, 1024>>>(rowlog, rowcnt, out);
}

// round 2
// speedup vs baseline: 1.0004x; 1.0004x over previous
#include <cuda_runtime.h>
#include <cuda_bf16.h>
#include <math.h>

// Problem constants
#define BATCH 1024
#define ZDIM  512
#define ADIM  8
#define AH    64
#define ZH    512
#define NNEG  100           // shifts 1..99 -> 99 extra columns
#define NCOLS 1123          // 1024 + 99
#define LDSIM 1152          // padded row stride for sim_mat

// ---------------- device scratch (no allocs allowed) ----------------
__device__ float d_ha0[BATCH * AH];
__device__ float d_g[BATCH * ZH];
__device__ float d_zwb[BATCH * ZH];
__device__ float d_u[BATCH * ZDIM];
__device__ float d_simmat[BATCH * LDSIM];
__device__ float d_rowlog[BATCH];
__device__ int   d_rowcnt[BATCH];

// ---------------- ha0 = relu(actions @ Wa + ba) ----------------
__global__ void k_ha0(const float* __restrict__ actions,
                      const float* __restrict__ Wa,
                      const float* __restrict__ ba,
                      float* __restrict__ ha0) {
    int b = blockIdx.x;
    int h = threadIdx.x;   // 64 threads
    float s = ba[h];
#pragma unroll
    for (int a = 0; a < ADIM; a++)
        s += actions[b * ADIM + a] * Wa[a * AH + h];
    ha0[b * AH + h] = fmaxf(s, 0.f);
}

// ---------------- generic fp32 GEMM, 64x64x16 tile, 4x4 microtile ----------------
// C[M,N] = A[M,K] @ (TRANSB ? B^T : B) (+ bias[n] if BIAS)
// TRANSB: B is [N,K] row-major. else B is [K,N] row-major.
template <bool TRANSB, bool BIAS>
__global__ void gemm64(const float* __restrict__ A, const float* __restrict__ B,
                       const float* __restrict__ bias, float* __restrict__ C,
                       int M, int N, int K, int lda, int ldb, int ldc) {
    __shared__ float As[16][65];
    __shared__ float Bs[16][65];

    const int tid = threadIdx.x;          // 256 threads
    const int tx = tid & 15;              // n micro index
    const int ty = tid >> 4;              // m micro index
    const int m0 = blockIdx.y * 64;
    const int n0 = blockIdx.x * 64;

    // A-tile loader indices: 64 rows x 16 cols as float4
    const int ar = tid >> 2;              // 0..63
    const int ac = (tid & 3) * 4;         // 0,4,8,12
    // B-tile (NN) loader: 16 rows x 64 cols as float4
    const int br = tid >> 4;              // 0..15
    const int bc = (tid & 15) * 4;        // 0..60

    float acc[4][4];
#pragma unroll
    for (int i = 0; i < 4; i++)
#pragma unroll
        for (int j = 0; j < 4; j++) acc[i][j] = 0.f;

    for (int k0 = 0; k0 < K; k0 += 16) {
        float4 av = *(const float4*)(A + (size_t)(m0 + ar) * lda + k0 + ac);
        As[ac + 0][ar] = av.x; As[ac + 1][ar] = av.y;
        As[ac + 2][ar] = av.z; As[ac + 3][ar] = av.w;
        if (TRANSB) {
            float4 bv = *(const float4*)(B + (size_t)(n0 + ar) * ldb + k0 + ac);
            Bs[ac + 0][ar] = bv.x; Bs[ac + 1][ar] = bv.y;
            Bs[ac + 2][ar] = bv.z; Bs[ac + 3][ar] = bv.w;
        } else {
            float4 bv = *(const float4*)(B + (size_t)(k0 + br) * ldb + n0 + bc);
            Bs[br][bc + 0] = bv.x; Bs[br][bc + 1] = bv.y;
            Bs[br][bc + 2] = bv.z; Bs[br][bc + 3] = bv.w;
        }
        __syncthreads();
#pragma unroll
        for (int kk = 0; kk < 16; kk++) {
            float ra[4], rb[4];
#pragma unroll
            for (int i = 0; i < 4; i++) ra[i] = As[kk][ty * 4 + i];
#pragma unroll
            for (int j = 0; j < 4; j++) rb[j] = Bs[kk][tx * 4 + j];
#pragma unroll
            for (int i = 0; i < 4; i++)
#pragma unroll
                for (int j = 0; j < 4; j++) acc[i][j] += ra[i] * rb[j];
        }
        __syncthreads();
    }

#pragma unroll
    for (int i = 0; i < 4; i++) {
#pragma unroll
        for (int j = 0; j < 4; j++) {
            float v = acc[i][j];
            int n = n0 + tx * 4 + j;
            if (BIAS) v += bias[n];
            C[(size_t)(m0 + ty * 4 + i) * ldc + n] = v;
        }
    }
}

// ---------------- neg_sim: sim_mat[b, 1024+i-1] ----------------
// neg_sim[b,i] = dot(z[b],z_next[b]) + dot(b2,z_next[b])
//              + sum_k relu(zwb[b,k] + g[(b+i)%B, k]) * u[b,k]
__global__ void k_neg(const float* __restrict__ z, const float* __restrict__ zn,
                      const float* __restrict__ b2,
                      const float* __restrict__ zwb, const float* __restrict__ g,
                      const float* __restrict__ u, float* __restrict__ simmat) {
    int b = blockIdx.x;
    int tid = threadIdx.x;   // 256
    __shared__ float s_zwb[ZH];
    __shared__ float s_u[ZH];
    __shared__ float red[8];
    __shared__ float s_base;

    float czz = 0.f, bz = 0.f;
    for (int k = tid; k < ZH; k += 256) {
        float znv = zn[b * ZDIM + k];
        czz += z[b * ZDIM + k] * znv;
        bz  += b2[k] * znv;
        s_zwb[k] = zwb[b * ZH + k];
        s_u[k]   = u[b * ZDIM + k];
    }
    float t = czz + bz;
#pragma unroll
    for (int o = 16; o; o >>= 1) t += __shfl_xor_sync(0xffffffffu, t, o);
    if ((tid & 31) == 0) red[tid >> 5] = t;
    __syncthreads();
    if (tid == 0) {
        float s = 0.f;
#pragma unroll
        for (int w = 0; w < 8; w++) s += red[w];
        s_base = s;
    }
    __syncthreads();
    float base = s_base;

    int wid = tid >> 5, lane = tid & 31;
    for (int i = 1 + wid; i < NNEG; i += 8) {
        int row = (b + i) & (BATCH - 1);
        const float* gr = g + (size_t)row * ZH;
        float p = 0.f;
#pragma unroll
        for (int k = lane; k < ZH; k += 32)
            p += fmaxf(s_zwb[k] + gr[k], 0.f) * s_u[k];
#pragma unroll
        for (int o = 16; o; o >>= 1) p += __shfl_xor_sync(0xffffffffu, p, o);
        if (lane == 0) simmat[(size_t)b * LDSIM + (BATCH - 1) + i] = base + p;
    }
}

// ---------------- per-row log-softmax diag + rank count ----------------
__global__ void k_row(const float* __restrict__ simmat,
                      float* __restrict__ rowlog, int* __restrict__ rowcnt) {
    int b = blockIdx.x;
    int tid = threadIdx.x;   // 256
    const float* row = simmat + (size_t)b * LDSIM;
    float s = row[b];

    __shared__ float smx[8];
    __shared__ int   scn[8];
    __shared__ float ssm[8];
    __shared__ float s_mx;

    float mx = -INFINITY;
    int cnt = 0;
    for (int j = tid; j < NCOLS; j += 256) {
        float v = row[j];
        mx = fmaxf(mx, v);
        cnt += (v > s) || (v == s && j < b);
    }
#pragma unroll
    for (int o = 16; o; o >>= 1) {
        mx = fmaxf(mx, __shfl_xor_sync(0xffffffffu, mx, o));
        cnt += __shfl_xor_sync(0xffffffffu, cnt, o);
    }
    if ((tid & 31) == 0) { smx[tid >> 5] = mx; scn[tid >> 5] = cnt; }
    __syncthreads();
    if (tid == 0) {
        float m = smx[0]; int c = scn[0];
#pragma unroll
        for (int w = 1; w < 8; w++) { m = fmaxf(m, smx[w]); c += scn[w]; }
        s_mx = m;
        rowcnt[b] = c;
    }
    __syncthreads();
    float m = s_mx;

    float se = 0.f;
    for (int j = tid; j < NCOLS; j += 256)
        se += __expf((row[j] - m) * 10.f);
#pragma unroll
    for (int o = 16; o; o >>= 1) se += __shfl_xor_sync(0xffffffffu, se, o);
    if ((tid & 31) == 0) ssm[tid >> 5] = se;
    __syncthreads();
    if (tid == 0) {
        float t = 0.f;
#pragma unroll
        for (int w = 0; w < 8; w++) t += ssm[w];
        // logp[b,b] = s/T - (m/T + log(sum exp((v-m)/T)))
        rowlog[b] = (s - m) * 10.f - logf(t);
    }
}

// ---------------- final reduction over rows ----------------
__global__ void k_final(const float* __restrict__ rowlog,
                        const int* __restrict__ rowcnt,
                        float* __restrict__ out) {
    int tid = threadIdx.x;  // 1024
    float lg = rowlog[tid];
    int c = rowcnt[tid];
    float a1 = (c < 1) ? 1.f : 0.f;
    float a3 = (c < 3) ? 1.f : 0.f;
    float a10 = (c < 10) ? 1.f : 0.f;

    __shared__ float s0[32], s1[32], s2[32], s3[32];
#pragma unroll
    for (int o = 16; o; o >>= 1) {
        lg  += __shfl_xor_sync(0xffffffffu, lg, o);
        a1  += __shfl_xor_sync(0xffffffffu, a1, o);
        a3  += __shfl_xor_sync(0xffffffffu, a3, o);
        a10 += __shfl_xor_sync(0xffffffffu, a10, o);
    }
    int wid = tid >> 5, lane = tid & 31;
    if (lane == 0) { s0[wid] = lg; s1[wid] = a1; s2[wid] = a3; s3[wid] = a10; }
    __syncthreads();
    if (wid == 0) {
        float v0 = s0[lane], v1 = s1[lane], v2 = s2[lane], v3 = s3[lane];
#pragma unroll
        for (int o = 16; o; o >>= 1) {
            v0 += __shfl_xor_sync(0xffffffffu, v0, o);
            v1 += __shfl_xor_sync(0xffffffffu, v1, o);
            v2 += __shfl_xor_sync(0xffffffffu, v2, o);
            v3 += __shfl_xor_sync(0xffffffffu, v3, o);
        }
        if (lane == 0) {
            out[0] = -v0 / (float)BATCH;
            out[1] = v1 / (float)BATCH;
            out[2] = v2 / (float)BATCH;
            out[3] = v3 / (float)BATCH;
        }
    }
}

// ---------------- launch ----------------
extern "C" void kernel_launch(void* const* d_in, const int* in_sizes, int n_in,
                              void* d_out, int out_size) {
    const float* z          = (const float*)d_in[0];
    const float* z_next     = (const float*)d_in[1];
    const float* z_next_hat = (const float*)d_in[2];
    const float* actions    = (const float*)d_in[3];
    const float* Wa         = (const float*)d_in[4];
    const float* ba         = (const float*)d_in[5];
    const float* W1         = (const float*)d_in[6];
    const float* b1         = (const float*)d_in[7];
    const float* W2         = (const float*)d_in[8];
    const float* b2         = (const float*)d_in[9];
    float* out = (float*)d_out;

    float *ha0, *g, *zwb, *u, *simmat, *rowlog;
    int* rowcnt;
    cudaGetSymbolAddress((void**)&ha0, d_ha0);
    cudaGetSymbolAddress((void**)&g, d_g);
    cudaGetSymbolAddress((void**)&zwb, d_zwb);
    cudaGetSymbolAddress((void**)&u, d_u);
    cudaGetSymbolAddress((void**)&simmat, d_simmat);
    cudaGetSymbolAddress((void**)&rowlog, d_rowlog);
    cudaGetSymbolAddress((void**)&rowcnt, d_rowcnt);

    // 1. ha0 = relu(actions @ Wa + ba)           [1024, 64]
    k_ha0<<<BATCH, AH>>>(actions, Wa, ba, ha0);

    // 2. g = ha0 @ W1[512:576, :]                [1024, 512]
    gemm64<false, false><<<dim3(ZH / 64, BATCH / 64), 256>>>(
        ha0, W1 + (size_t)ZDIM * ZH, nullptr, g, BATCH, ZH, AH, AH, ZH, ZH);

    // 3. zwb = z @ W1[0:512, :] + b1             [1024, 512]
    gemm64<false, true><<<dim3(ZH / 64, BATCH / 64), 256>>>(
        z, W1, b1, zwb, BATCH, ZH, ZDIM, ZDIM, ZH, ZH);

    // 4. u = z_next @ W2^T                       [1024, 512]
    gemm64<true, false><<<dim3(ZDIM / 64, BATCH / 64), 256>>>(
        z_next, W2, nullptr, u, BATCH, ZDIM, ZH, ZDIM, ZH, ZDIM);

    // 5. sim = z_next @ z_next_hat^T -> simmat[:, 0:1024]
    gemm64<true, false><<<dim3(BATCH / 64, BATCH / 64), 256>>>(
        z_next, z_next_hat, nullptr, simmat, BATCH, BATCH, ZDIM, ZDIM, ZDIM, LDSIM);

    // 6. neg_sim columns 1024..1122
    k_neg<<<BATCH, 256>>>(z, z_next, b2, zwb, g, u, simmat);

    // 7. per-row log-softmax diagonal + rank counts
    k_row<<<BATCH, 256>>>(simmat, rowlog, rowcnt);

    // 8. final scalar outputs
    k_final<<<1, 1024>>>(rowlog, rowcnt, out);
}